// round 15
// baseline (speedup 1.0000x reference)
#include <cuda_runtime.h>
#include <cstdint>

// sLSTM, T=512, B=16, HID=1024, H=4 heads (D=256), G=4 gates.
// R15 = R13 skeleton (cluster-of-8 DSMEM bulk exchange, rank-major tile,
// W in regs, f32x2 FMA, fast-math gates) with TPB 512 (16 warps):
// thread tile 2 gates x 4 batches x 32k -> 4 warps/SMSP for latency hiding,
// h LDS traffic halved via intra-warp broadcast, butterfly reduce-scatter.

#define T_STEPS 512
#define BATCH   16
#define HID     1024
#define TPB     512
#define SRS     17
#define CLUSTER 8
#define TXB     4096u    // 8 copies x 512 B per receiver per step

__device__ __forceinline__ void ffma2(unsigned long long &acc,
                                      unsigned long long a,
                                      unsigned long long b) {
    asm("fma.rn.f32x2 %0, %1, %2, %0;" : "+l"(acc) : "l"(a), "l"(b));
}
__device__ __forceinline__ float fold2(unsigned long long a) {
    return __uint_as_float((unsigned)(a & 0xffffffffu)) +
           __uint_as_float((unsigned)(a >> 32));
}
__device__ __forceinline__ uint32_t smem_u32(const void* p) {
    uint32_t a;
    asm("{ .reg .u64 t; cvta.to.shared.u64 t, %1; cvt.u32.u64 %0, t; }"
        : "=r"(a) : "l"(p));
    return a;
}
__device__ __forceinline__ uint32_t mapa_u32(uint32_t a, uint32_t rank) {
    uint32_t d;
    asm("mapa.shared::cluster.u32 %0, %1, %2;" : "=r"(d) : "r"(a), "r"(rank));
    return d;
}
__device__ __forceinline__ void bulk_copy_s2s(uint32_t dst_cluster, uint32_t src_cta,
                                              uint32_t bytes, uint32_t mbar_cluster) {
    asm volatile(
        "cp.async.bulk.shared::cluster.shared::cta.mbarrier::complete_tx::bytes "
        "[%0], [%1], %2, [%3];"
        :: "r"(dst_cluster), "r"(src_cta), "r"(bytes), "r"(mbar_cluster) : "memory");
}
__device__ __forceinline__ void mbar_init(uint32_t mbar, uint32_t cnt) {
    asm volatile("mbarrier.init.shared.b64 [%0], %1;" :: "r"(mbar), "r"(cnt) : "memory");
}
__device__ __forceinline__ void mbar_expect_tx(uint32_t mbar, uint32_t bytes) {
    asm volatile("mbarrier.arrive.expect_tx.shared.b64 _, [%0], %1;"
                 :: "r"(mbar), "r"(bytes) : "memory");
}
__device__ __forceinline__ void mbar_wait(uint32_t mbar, uint32_t parity) {
    uint32_t done;
    asm volatile(
        "{\n\t.reg .pred p;\n\t"
        "mbarrier.try_wait.parity.acquire.cta.shared::cta.b64 p, [%1], %2;\n\t"
        "selp.b32 %0, 1, 0, p;\n\t}"
        : "=r"(done) : "r"(mbar), "r"(parity) : "memory");
    if (!done) {
        asm volatile(
            "{\n\t.reg .pred P1;\n\t"
            "WL_%=:\n\t"
            "mbarrier.try_wait.parity.acquire.cta.shared::cta.b64 P1, [%0], %1, 0x989680;\n\t"
            "@P1 bra.uni WD_%=;\n\t"
            "bra.uni WL_%=;\n\t"
            "WD_%=:\n\t}"
            :: "r"(mbar), "r"(parity) : "memory");
    }
}
__device__ __forceinline__ void fence_proxy_async_cta() {
    asm volatile("fence.proxy.async.shared::cta;" ::: "memory");
}
__device__ __forceinline__ uint32_t elect_one() {
    uint32_t pred;
    asm volatile(
        "{\n\t.reg .pred p;\n\t"
        "elect.sync _|p, 0xFFFFFFFF;\n\t"
        "selp.b32 %0, 1, 0, p;\n\t}"
        : "=r"(pred));
    return pred;
}

struct St { float h, c, n, m; };

__device__ __forceinline__ float gate_update(St &s, float iraw, float fraw,
                                             float zraw, float oraw, int t) {
    float e   = __expf(-fabsf(fraw));
    float lf  = s.m + (fraw < 0.f ? fraw : 0.f) - __logf(1.f + e);
    float mn  = (t == 0) ? iraw : fmaxf(iraw, lf);   // all(n==0) only at t=0
    float og  = __fdividef(1.f, 1.f + __expf(-oraw));
    float ig  = __expf(iraw - mn);
    float fg  = __expf(lf - mn);
    float t2  = __expf(2.f * zraw);                  // tanh(z) = 1 - 2/(1+e^{2z})
    float th  = 1.f - __fdividef(2.f, t2 + 1.f);
    float cn  = fg * s.c + ig * th;
    float nn  = fg * s.h + ig;                       // reference uses h here
    float hn  = __fdividef(og * cn, nn);
    s.c = cn; s.n = nn; s.m = mn; s.h = hn;
    return hn;
}

__global__ __launch_bounds__(TPB, 1) __cluster_dims__(CLUSTER, 1, 1)
void slstm_kernel(
    const float* __restrict__ x,     // (512, 16, 4096)
    const float* __restrict__ rk,    // (4, 256, 4, 256)
    const float* __restrict__ bias,  // flat 4096
    float* __restrict__ out)         // outs (512,16,1024) ++ final (4,16,1024)
{
    // h tile, double-buffered, rank-major: [buf][rank(8)][bl(4)][8 float4]
    __shared__ float4 sT[2][256];
    // outgoing h staging: [buf][bl(4)][8 float4] = 512 B each
    __shared__ float4 sStage[2][32];
    __shared__ float  sRaw[32 * SRS + 4];
    __shared__ unsigned long long mbar[2];

    const int c     = blockIdx.x;      // cluster = (head, bg), rank = cg
    const int head  = c >> 5;
    const int bg    = (c >> 3) & 3;
    const int cg    = c & 7;
    const int dd0   = cg << 5;
    const int b0    = bg << 2;
    const int hbase = head << 8;
    const int tid   = threadIdx.x;
    const int wq    = tid >> 5;        // 0..15
    const int lane  = tid & 31;
    const int ks    = lane >> 2;       // k-slice == producer rank
    const int gh    = (lane >> 1) & 1; // gate half: gates {2gh, 2gh+1}
    const int c2    = lane & 1;        // channel within warp
    const int ch_t  = (wq << 1) + c2;  // GEMM channel (0..31)
    const int s0    = ks & 1, s1 = (ks >> 1) & 1, s2 = (ks >> 2) & 1;

    // ---- one-time W gather into registers (verified formula, gates 2gh..2gh+1) ----
    float Wf[64];   // [(gl*8+j)*4 + e], gate = 2gh+gl, d = 32ks + 4j + e
    {
        const int dd  = dd0 + ch_t;
        const int gx  = dd >> 6;
        const int bbs = (dd & 63) << 2;
        #pragma unroll
        for (int gl = 0; gl < 2; ++gl) {
            const int gate = (gh << 1) + gl;
            #pragma unroll
            for (int j = 0; j < 8; ++j)
                #pragma unroll
                for (int e = 0; e < 4; ++e) {
                    int d  = 32 * ks + 4 * j + e;
                    int a  = ((d & 63) << 2) + gate;
                    int bb = bbs + (d >> 6);
                    Wf[(gl * 8 + j) * 4 + e] =
                        __ldg(&rk[((hbase + a) * 4 + gx) * 256 + bb]);
                }
        }
    }
    const unsigned long long* W2 = (const unsigned long long*)Wf;

    // ---- elementwise role: tid<128 owns (channel ch_u, batch b0+bl_u) ----
    const int ch_u = tid >> 2;
    const int bl_u = tid & 3;
    const int q_u  = hbase + dd0 + ch_u;
    float bias_g[4];
    #pragma unroll
    for (int g = 0; g < 4; ++g) bias_g[g] = bias[(g << 10) + q_u];
    St st = {0.f, 0.f, 0.f, 0.f};

    // staging float index (R13-verified): f4 slot bl*8 + ((ch>>2)^cg), elem ch&3
    const int stageIdx = ((bl_u << 3) + (((ch_u >> 2) ^ cg) & 7)) * 4 + (ch_u & 3);

    const uint32_t tileAddr  = smem_u32(&sT[0][0]);
    const uint32_t stageAddr = smem_u32(&sStage[0][0]);
    const uint32_t mbarAddr  = smem_u32(&mbar[0]);
    // warps 0..7 push to rank wq
    const uint32_t rTile = mapa_u32(tileAddr, (uint32_t)(wq & 7)) + (uint32_t)(cg * 512);
    const uint32_t rMbar = mapa_u32(mbarAddr, (uint32_t)(wq & 7));

    if (tid == 0) { mbar_init(mbarAddr, 1); mbar_init(mbarAddr + 8, 1); }
    {
        float4 z = make_float4(0.f, 0.f, 0.f, 0.f);
        for (int i = tid; i < 256; i += TPB) sT[0][i] = z;
    }
    __syncthreads();
    asm volatile("barrier.cluster.arrive.aligned;" ::: "memory");
    asm volatile("barrier.cluster.wait.aligned;"   ::: "memory");

    int ph0 = 0, ph1 = 0;
    const unsigned long long* sT2 = (const unsigned long long*)&sT[0][0];

    for (int t = 0; t < T_STEPS; ++t) {
        const int nb = t & 1;

        // x load for this step (issued pre-wait; latency overlaps the wait)
        float xr[4];
        if (tid < 128) {
            const float* xb = x + (size_t)(t * BATCH + b0 + bl_u) * 4096 + q_u;
            #pragma unroll
            for (int g = 0; g < 4; ++g) xr[g] = __ldg(xb + (g << 10));
        }

        if (t > 0) {
            mbar_wait(mbarAddr + nb * 8, nb ? ph1 : ph0);
            if (nb) ph1 ^= 1; else ph0 ^= 1;
        }
        if (tid == 0 && t + 1 < T_STEPS)
            mbar_expect_tx(mbarAddr + ((t + 1) & 1) * 8, TXB);

        // ---- GEMM: 2 gates x 4 batches, k-slice = rank ks ----
        // (gh lanes share h addresses -> intra-warp broadcast, 128B/warp-LDS)
        const unsigned long long* sB = sT2 + nb * (256 * 2);
        unsigned long long acc[8];
        #pragma unroll
        for (int q = 0; q < 8; ++q) acc[q] = 0ull;
        #pragma unroll
        for (int j = 0; j < 8; ++j) {
            int jj = (j ^ ks) & 7;
            unsigned long long wlo0 = W2[(0 * 8 + j) * 2];
            unsigned long long whi0 = W2[(0 * 8 + j) * 2 + 1];
            unsigned long long wlo1 = W2[(1 * 8 + j) * 2];
            unsigned long long whi1 = W2[(1 * 8 + j) * 2 + 1];
            #pragma unroll
            for (int bl = 0; bl < 4; ++bl) {
                int idx = ((ks << 5) + (bl << 3) + jj) << 1;
                unsigned long long hlo = sB[idx];
                unsigned long long hhi = sB[idx + 1];
                ffma2(acc[bl],     wlo0, hlo);
                ffma2(acc[bl],     whi0, hhi);
                ffma2(acc[4 + bl], wlo1, hlo);
                ffma2(acc[4 + bl], whi1, hhi);
            }
        }

        // ---- butterfly reduce-scatter over ks (masks 4, 8, 16) ----
        {
            float v[8];
            #pragma unroll
            for (int q = 0; q < 8; ++q) {
                // v[gl*4+bl]; reindex so level-1 reduces gl: v[k] k<4 -> gl0
                v[q] = fold2(acc[q]);
            }
            float w[4];
            #pragma unroll
            for (int k = 0; k < 4; ++k) {
                float send = s0 ? v[k] : v[k + 4];
                float keep = s0 ? v[k + 4] : v[k];
                w[k] = keep + __shfl_xor_sync(0xffffffffu, send, 4);
            }
            float u[2];
            #pragma unroll
            for (int k = 0; k < 2; ++k) {
                float send = s1 ? w[k] : w[k + 2];
                float keep = s1 ? w[k + 2] : w[k];
                u[k] = keep + __shfl_xor_sync(0xffffffffu, send, 8);
            }
            {
                float send = s2 ? u[0] : u[1];
                float keep = s2 ? u[1] : u[0];
                float z = keep + __shfl_xor_sync(0xffffffffu, send, 16);
                // this lane holds (gate = 2gh + s0, bl = 2s1 + s2)
                int gate = (gh << 1) + s0;
                int bl   = (s1 << 1) + s2;
                sRaw[ch_t * SRS + gate * 4 + bl] = z;
            }
        }
        __syncthreads();

        // ---- elementwise (tid<128) -> staging + out ----
        if (tid < 128) {
            const float* rw = &sRaw[ch_u * SRS + bl_u];
            float iraw = rw[ 0] + xr[0] + bias_g[0];
            float fraw = rw[ 4] + xr[1] + bias_g[1];
            float zraw = rw[ 8] + xr[2] + bias_g[2];
            float oraw = rw[12] + xr[3] + bias_g[3];
            float hn = gate_update(st, iraw, fraw, zraw, oraw, t);
            ((float*)&sStage[nb][0])[stageIdx] = hn;
            __stcg(&out[(size_t)(t * BATCH + b0 + bl_u) * HID + q_u], hn);
        }
        __syncthreads();

        // ---- parallel push: warps 0..7, warp wq copies 512B to rank wq ----
        if (wq < 8 && t + 1 < T_STEPS) {
            if (elect_one()) {
                fence_proxy_async_cta();
                bulk_copy_s2s(rTile + (uint32_t)(((t + 1) & 1) * 4096),
                              stageAddr + (uint32_t)nb * 512u,
                              512u,
                              rMbar + (uint32_t)(((t + 1) & 1) * 8));
            }
        }
    }

    if (tid < 128) {
        const size_t FS = (size_t)T_STEPS * BATCH * HID;
        const size_t o  = (size_t)(b0 + bl_u) * HID + q_u;
        out[FS + 0 * BATCH * HID + o] = st.h;
        out[FS + 1 * BATCH * HID + o] = st.c;
        out[FS + 2 * BATCH * HID + o] = st.n;
        out[FS + 3 * BATCH * HID + o] = st.m;
    }
    // last-step pushes skipped -> nothing in flight at exit
}

extern "C" void kernel_launch(void* const* d_in, const int* in_sizes, int n_in,
                              void* d_out, int out_size) {
    const float* x    = (const float*)d_in[0];
    const float* rk   = (const float*)d_in[1];
    const float* bias = (const float*)d_in[2];
    float* out        = (float*)d_out;

    slstm_kernel<<<128, TPB>>>(x, rk, bias, out);
}

// round 16
// speedup vs baseline: 1.1989x; 1.1989x over previous
#include <cuda_runtime.h>
#include <cstdint>

// sLSTM, T=512, B=16, HID=1024, H=4 heads (D=256), G=4 gates.
// R16: warp-autonomous steps. Cluster-of-8 DSMEM exchange as R13, but NO
// __syncthreads in the loop: each warp does GEMM -> shfl reduce-scatter ->
// shfl gate-gather -> gate update -> STS 64B slice -> 8x 64B bulk copies.
// Tile [rank][slot=j^ks][bl] is conflict-free per phase AND makes each
// warp's outgoing slice contiguous. Only sync = per-CTA mbarrier wait.

#define T_STEPS 512
#define BATCH   16
#define HID     1024
#define TPB     256
#define CLUSTER 8
#define TXB     4096u    // 8 CTAs x 8 warps x 64 B per receiver per step

__device__ __forceinline__ void ffma2(unsigned long long &acc,
                                      unsigned long long a,
                                      unsigned long long b) {
    asm("fma.rn.f32x2 %0, %1, %2, %0;" : "+l"(acc) : "l"(a), "l"(b));
}
__device__ __forceinline__ float fold2(unsigned long long a) {
    return __uint_as_float((unsigned)(a & 0xffffffffu)) +
           __uint_as_float((unsigned)(a >> 32));
}
__device__ __forceinline__ uint32_t smem_u32(const void* p) {
    uint32_t a;
    asm("{ .reg .u64 t; cvta.to.shared.u64 t, %1; cvt.u32.u64 %0, t; }"
        : "=r"(a) : "l"(p));
    return a;
}
__device__ __forceinline__ uint32_t mapa_u32(uint32_t a, uint32_t rank) {
    uint32_t d;
    asm("mapa.shared::cluster.u32 %0, %1, %2;" : "=r"(d) : "r"(a), "r"(rank));
    return d;
}
__device__ __forceinline__ void bulk_copy_s2s(uint32_t dst_cluster, uint32_t src_cta,
                                              uint32_t bytes, uint32_t mbar_cluster) {
    asm volatile(
        "cp.async.bulk.shared::cluster.shared::cta.mbarrier::complete_tx::bytes "
        "[%0], [%1], %2, [%3];"
        :: "r"(dst_cluster), "r"(src_cta), "r"(bytes), "r"(mbar_cluster) : "memory");
}
__device__ __forceinline__ void mbar_init(uint32_t mbar, uint32_t cnt) {
    asm volatile("mbarrier.init.shared.b64 [%0], %1;" :: "r"(mbar), "r"(cnt) : "memory");
}
__device__ __forceinline__ void mbar_expect_tx(uint32_t mbar, uint32_t bytes) {
    asm volatile("mbarrier.arrive.expect_tx.shared.b64 _, [%0], %1;"
                 :: "r"(mbar), "r"(bytes) : "memory");
}
__device__ __forceinline__ void mbar_wait(uint32_t mbar, uint32_t parity) {
    uint32_t done;
    asm volatile(
        "{\n\t.reg .pred p;\n\t"
        "mbarrier.try_wait.parity.acquire.cta.shared::cta.b64 p, [%1], %2;\n\t"
        "selp.b32 %0, 1, 0, p;\n\t}"
        : "=r"(done) : "r"(mbar), "r"(parity) : "memory");
    if (!done) {
        asm volatile(
            "{\n\t.reg .pred P1;\n\t"
            "WL_%=:\n\t"
            "mbarrier.try_wait.parity.acquire.cta.shared::cta.b64 P1, [%0], %1, 0x989680;\n\t"
            "@P1 bra.uni WD_%=;\n\t"
            "bra.uni WL_%=;\n\t"
            "WD_%=:\n\t}"
            :: "r"(mbar), "r"(parity) : "memory");
    }
}
__device__ __forceinline__ void fence_proxy_async_cta() {
    asm volatile("fence.proxy.async.shared::cta;" ::: "memory");
}

struct St { float h, c, n, m; };

__device__ __forceinline__ float gate_update(St &s, float iraw, float fraw,
                                             float zraw, float oraw, int t) {
    float e   = __expf(-fabsf(fraw));
    float lf  = s.m + (fraw < 0.f ? fraw : 0.f) - __logf(1.f + e);
    float mn  = (t == 0) ? iraw : fmaxf(iraw, lf);   // all(n==0) only at t=0
    float og  = __fdividef(1.f, 1.f + __expf(-oraw));
    float ig  = __expf(iraw - mn);
    float fg  = __expf(lf - mn);
    float t2  = __expf(2.f * zraw);                  // tanh(z) = 1 - 2/(1+e^{2z})
    float th  = 1.f - __fdividef(2.f, t2 + 1.f);
    float cn  = fg * s.c + ig * th;
    float nn  = fg * s.h + ig;                       // reference uses h here
    float hn  = __fdividef(og * cn, nn);
    s.c = cn; s.n = nn; s.m = mn; s.h = hn;
    return hn;
}

__global__ __launch_bounds__(TPB, 1) __cluster_dims__(CLUSTER, 1, 1)
void slstm_kernel(
    const float* __restrict__ x,     // (512, 16, 4096)
    const float* __restrict__ rk,    // (4, 256, 4, 256)
    const float* __restrict__ bias,  // flat 4096
    float* __restrict__ out)         // outs (512,16,1024) ++ final (4,16,1024)
{
    // h tile, double-buffered: [buf][rank(8)][slot(8)][bl(4)] float4
    // slot = logical_chgrp ^ rank  (conflict-free per phase; writer-contiguous)
    __shared__ float4 sT[2][256];
    // outgoing staging: [buf][warp(8)][bl(4)] float4 = 64 B per warp
    __shared__ float4 sStage[2][32];
    __shared__ unsigned long long mbar[2];

    const int c     = blockIdx.x;      // cluster = (head, bg), rank = cg
    const int head  = c >> 5;
    const int bg    = (c >> 3) & 3;
    const int cg    = c & 7;
    const int dd0   = cg << 5;
    const int b0    = bg << 2;
    const int hbase = head << 8;
    const int tid   = threadIdx.x;
    const int wq    = tid >> 5;        // 8 warps; warp owns channels 4wq..4wq+3
    const int lane  = tid & 31;
    const int rq    = lane & 3;        // channel within warp
    const int ks    = lane >> 2;       // k-slice == source rank
    const int ch_t  = (wq << 2) + rq;  // this lane's channel (0..31)
    const int s0    = ks & 1, s1 = (ks >> 1) & 1, s2 = (ks >> 2) & 1;

    // ---- one-time W gather into registers (R8/R13-verified formula) ----
    float Wf[128];   // [(i*8+j)*4 + e], gate i, d = 32ks + 4j + e
    {
        const int dd  = dd0 + ch_t;
        const int gx  = dd >> 6;
        const int bbs = (dd & 63) << 2;
        #pragma unroll
        for (int i = 0; i < 4; ++i)
            #pragma unroll
            for (int j = 0; j < 8; ++j)
                #pragma unroll
                for (int e = 0; e < 4; ++e) {
                    int d  = 32 * ks + 4 * j + e;
                    int a  = ((d & 63) << 2) + i;
                    int bb = bbs + (d >> 6);
                    Wf[(i * 8 + j) * 4 + e] =
                        __ldg(&rk[((hbase + a) * 4 + gx) * 256 + bb]);
                }
    }
    const unsigned long long* W2 = (const unsigned long long*)Wf;

    // ---- owner role: lanes with s1==0 own cell (ch_t, bl = 2s2+s0) ----
    const bool owner = (s1 == 0);
    const int  bl_o  = (s2 << 1) + s0;
    const int  q_o   = hbase + dd0 + ch_t;
    float bias_g[4];
    #pragma unroll
    for (int g = 0; g < 4; ++g) bias_g[g] = bias[(g << 10) + q_o];
    St st = {0.f, 0.f, 0.f, 0.f};

    const uint32_t tileAddr  = smem_u32(&sT[0][0]);
    const uint32_t stageAddr = smem_u32(&sStage[0][0]);
    const uint32_t mbarAddr  = smem_u32(&mbar[0]);
    // lane r<8 pushes this warp's 64B slice to rank r
    const uint32_t rTileL = mapa_u32(tileAddr, (uint32_t)(lane & 7))
                          + (uint32_t)(cg * 512 + (((wq ^ cg) & 7) << 6));
    const uint32_t rMbarL = mapa_u32(mbarAddr, (uint32_t)(lane & 7));
    const uint32_t srcW   = stageAddr + (uint32_t)(wq << 6);

    if (tid == 0) { mbar_init(mbarAddr, 1); mbar_init(mbarAddr + 8, 1); }
    {
        float4 z4 = make_float4(0.f, 0.f, 0.f, 0.f);
        for (int i = tid; i < 256; i += TPB) sT[0][i] = z4;
    }
    __syncthreads();
    asm volatile("barrier.cluster.arrive.aligned;" ::: "memory");
    asm volatile("barrier.cluster.wait.aligned;"   ::: "memory");

    int ph0 = 0, ph1 = 0;
    const unsigned long long* sT2 = (const unsigned long long*)&sT[0][0];

    for (int t = 0; t < T_STEPS; ++t) {
        const int nb = t & 1;

        // warp 0 lane 0 arms the next buffer (signed tx: arrivals may precede)
        if (tid == 0 && t + 1 < T_STEPS)
            mbar_expect_tx(mbarAddr + ((t + 1) & 1) * 8, TXB);

        // owners prefetch x (issued pre-wait; consumed post-GEMM)
        float xr[4];
        if (owner) {
            const float* xb = x + (size_t)(t * BATCH + b0 + bl_o) * 4096 + q_o;
            #pragma unroll
            for (int g = 0; g < 4; ++g) xr[g] = __ldg(xb + (g << 10));
        }

        if (t > 0) {
            mbar_wait(mbarAddr + nb * 8, nb ? ph1 : ph0);
            if (nb) ph1 ^= 1; else ph0 ^= 1;
        }

        // ---- GEMM: 4 gates x 4 batches for ch_t, k-slice = rank ks ----
        const unsigned long long* sB = sT2 + nb * 512;
        unsigned long long acc[16];
        #pragma unroll
        for (int q = 0; q < 16; ++q) acc[q] = 0ull;
        #pragma unroll
        for (int j = 0; j < 8; ++j) {
            const int slot = (j ^ ks) & 7;
            unsigned long long hlo[4], hhi[4];
            #pragma unroll
            for (int bl = 0; bl < 4; ++bl) {
                int idx = ((ks << 5) + (slot << 2) + bl) << 1;
                hlo[bl] = sB[idx];
                hhi[bl] = sB[idx + 1];
            }
            #pragma unroll
            for (int i = 0; i < 4; ++i) {
                unsigned long long wlo = W2[(i * 8 + j) * 2];
                unsigned long long whi = W2[(i * 8 + j) * 2 + 1];
                #pragma unroll
                for (int bl = 0; bl < 4; ++bl) {
                    ffma2(acc[i * 4 + bl], wlo, hlo[bl]);
                    ffma2(acc[i * 4 + bl], whi, hhi[bl]);
                }
            }
        }

        // ---- butterfly reduce-scatter over ks (masks 4,8,16; R14-verified) ----
        float z0, z1;
        {
            float v[16];
            #pragma unroll
            for (int q = 0; q < 16; ++q) v[q] = fold2(acc[q]);
            float w[8];
            #pragma unroll
            for (int k = 0; k < 8; ++k) {
                float send = s0 ? v[k] : v[k + 8];
                float keep = s0 ? v[k + 8] : v[k];
                w[k] = keep + __shfl_xor_sync(0xffffffffu, send, 4);
            }
            float u[4];
            #pragma unroll
            for (int k = 0; k < 4; ++k) {
                float send = s1 ? w[k] : w[k + 4];
                float keep = s1 ? w[k + 4] : w[k];
                u[k] = keep + __shfl_xor_sync(0xffffffffu, send, 8);
            }
            {
                float send = s2 ? u[0] : u[2];
                float keep = s2 ? u[2] : u[0];
                z0 = keep + __shfl_xor_sync(0xffffffffu, send, 16);
            }
            {
                float send = s2 ? u[1] : u[3];
                float keep = s2 ? u[3] : u[1];
                z1 = keep + __shfl_xor_sync(0xffffffffu, send, 16);
            }
        }
        // lane now holds (gate i = 2s0+s1) for cells bl = 2s2+{0,1}: z0, z1

        // ---- gate gather: converge all 4 gates of cell bl=2s2+s0 on lane ----
        float keepA = s0 ? z1 : z0;                  // own z[s0]
        float sendA = s0 ? z0 : z1;                  // own z[s0^1] for partner
        float recvA = __shfl_xor_sync(0xffffffffu, sendA, 4);
        float recvB1 = __shfl_xor_sync(0xffffffffu, keepA, 8);
        float recvB2 = __shfl_xor_sync(0xffffffffu, recvA, 8);

        // ---- owners: gate update, stage, out ----
        if (owner) {
            float iraw = (s0 ? recvA  : keepA ) + xr[0] + bias_g[0];
            float fraw = (s0 ? recvB2 : recvB1) + xr[1] + bias_g[1];
            float zraw = (s0 ? keepA  : recvA ) + xr[2] + bias_g[2];
            float oraw = (s0 ? recvB1 : recvB2) + xr[3] + bias_g[3];
            float hn = gate_update(st, iraw, fraw, zraw, oraw, t);
            ((float*)&sStage[nb][0])[(wq << 4) + (bl_o << 2) + rq] = hn;
            __stcg(&out[(size_t)(t * BATCH + b0 + bl_o) * HID + q_o], hn);
        }
        __syncwarp();

        // ---- push this warp's 64B slice to all 8 ranks (lanes 0..7) ----
        if (t + 1 < T_STEPS) {
            fence_proxy_async_cta();
            if (lane < 8) {
                bulk_copy_s2s(rTileL + (uint32_t)(((t + 1) & 1) * 4096),
                              srcW + (uint32_t)(nb * 512),
                              64u,
                              rMbarL + (uint32_t)(((t + 1) & 1) * 8));
            }
        }
    }

    if (owner) {
        const size_t FS = (size_t)T_STEPS * BATCH * HID;
        const size_t o  = (size_t)(b0 + bl_o) * HID + q_o;
        out[FS + 0 * BATCH * HID + o] = st.h;
        out[FS + 1 * BATCH * HID + o] = st.c;
        out[FS + 2 * BATCH * HID + o] = st.n;
        out[FS + 3 * BATCH * HID + o] = st.m;
    }
    // last-step pushes skipped -> nothing in flight; cluster barrier for safe exit
    asm volatile("barrier.cluster.arrive.aligned;" ::: "memory");
    asm volatile("barrier.cluster.wait.aligned;"   ::: "memory");
}

extern "C" void kernel_launch(void* const* d_in, const int* in_sizes, int n_in,
                              void* d_out, int out_size) {
    const float* x    = (const float*)d_in[0];
    const float* rk   = (const float*)d_in[1];
    const float* bias = (const float*)d_in[2];
    float* out        = (float*)d_out;

    slstm_kernel<<<128, TPB>>>(x, rk, bias, out);
}